// round 5
// baseline (speedup 1.0000x reference)
#include <cuda_runtime.h>
#include <cuda_fp16.h>

#define D 64
#define MAXN 100000
#define MAXE 1200000
#define EPS 1e-12f
#define SCAN_BLK 1024
#define MAX_PART 128   // ceil(MAXN/SCAN_BLK) = 98

// Scratch (device globals — no allocation allowed in kernel_launch)
__device__ __half g_nh[(size_t)MAXN * D];  // normalized features fp16, 12.8 MB
__device__ float  g_norm[MAXN];            // per-node L2 norm
__device__ int    g_count[MAXN];           // in-degree histogram
__device__ int    g_off[MAXN];             // block-local exclusive offsets
__device__ int    g_partoff[MAX_PART];     // per-scan-block exclusive offsets
__device__ int    g_rank[MAXE];            // edge rank within its dst bucket
__device__ int    g_srcs[MAXE];            // src ids grouped by dst (CSR adj)

// ---------------------------------------------------------------------------
// K1: L2-normalize each row (16 lanes/node, float4/lane). Stores nh fp16 +
//     norm scalar, zeroes the in-degree counter.
// ---------------------------------------------------------------------------
__global__ void k_norm(const float* __restrict__ feat, int N) {
    int t = blockIdx.x * blockDim.x + threadIdx.x;
    int node = t >> 4, sub = t & 15;
    if (node >= N) return;
    float4 v = __ldg((const float4*)(feat + (size_t)node * D) + sub);
    float ss = v.x * v.x + v.y * v.y + v.z * v.z + v.w * v.w;
    #pragma unroll
    for (int o = 8; o; o >>= 1) ss += __shfl_xor_sync(0xffffffffu, ss, o);
    float nrm = fmaxf(sqrtf(ss), EPS);
    float inv = 1.0f / nrm;
    __half2 h0 = __floats2half2_rn(v.x * inv, v.y * inv);
    __half2 h1 = __floats2half2_rn(v.z * inv, v.w * inv);
    ((uint2*)(g_nh + (size_t)node * D))[sub] =
        make_uint2(*(const unsigned*)&h0, *(const unsigned*)&h1);
    if (sub == 0) { g_norm[node] = nrm; g_count[node] = 0; }
}

// ---------------------------------------------------------------------------
// K2: in-degree histogram; atomicAdd's return value assigns each edge a
//     stable slot (rank) inside its dst bucket.
// ---------------------------------------------------------------------------
__global__ void k_hist(const int* __restrict__ dst, int E) {
    int e = blockIdx.x * blockDim.x + threadIdx.x;
    if (e >= E) return;
    g_rank[e] = atomicAdd(&g_count[__ldg(dst + e)], 1);
}

// ---------------------------------------------------------------------------
// K3a: per-block inclusive scan (Hillis-Steele in smem) of counts;
//      writes block-local EXCLUSIVE offsets and the block total.
// ---------------------------------------------------------------------------
__global__ void k_scan1(int N) {
    __shared__ int sh[SCAN_BLK];
    int i = blockIdx.x * SCAN_BLK + threadIdx.x;
    int v = (i < N) ? g_count[i] : 0;
    sh[threadIdx.x] = v;
    __syncthreads();
    #pragma unroll
    for (int o = 1; o < SCAN_BLK; o <<= 1) {
        int t = (threadIdx.x >= o) ? sh[threadIdx.x - o] : 0;
        __syncthreads();
        sh[threadIdx.x] += t;
        __syncthreads();
    }
    if (i < N) g_off[i] = sh[threadIdx.x] - v;   // exclusive
    if (threadIdx.x == SCAN_BLK - 1) g_partoff[blockIdx.x] = sh[SCAN_BLK - 1];
}

// K3b: single block scans the (<=128) block totals into exclusive offsets.
__global__ void k_scan2(int nPart) {
    __shared__ int sh[MAX_PART];
    int v = (threadIdx.x < nPart) ? g_partoff[threadIdx.x] : 0;
    sh[threadIdx.x] = v;
    __syncthreads();
    #pragma unroll
    for (int o = 1; o < MAX_PART; o <<= 1) {
        int t = (threadIdx.x >= o) ? sh[threadIdx.x - o] : 0;
        __syncthreads();
        sh[threadIdx.x] += t;
        __syncthreads();
    }
    if (threadIdx.x < nPart) g_partoff[threadIdx.x] = sh[threadIdx.x] - v;
}

// ---------------------------------------------------------------------------
// K4: scatter src ids into dst-grouped order (counting sort payload pass).
// ---------------------------------------------------------------------------
__global__ void k_scatter(const int* __restrict__ src, const int* __restrict__ dst, int E) {
    int e = blockIdx.x * blockDim.x + threadIdx.x;
    if (e >= E) return;
    int d = __ldg(dst + e);
    int pos = g_off[d] + g_partoff[d >> 10] + g_rank[e];
    g_srcs[pos] = __ldg(src + e);
}

// ---------------------------------------------------------------------------
// K5: aggregation, 16 lanes per dst node, NO atomics.
//     nh[dst] loaded once into registers; loop over the node's incoming
//     edges: gather nh[src] (fp16, L2-resident), 16-lane shfl dot,
//     w = exp(beta*dot) (max-pass skipped: |beta*cos|<=|beta|), accumulate
//     w*norm[src]*nh[src] and w in registers. One float4 store per node:
//     out = acc / sum(w). Fully overwrites out (no memset / div pass).
// ---------------------------------------------------------------------------
__global__ void k_agg(const float* __restrict__ beta, float* __restrict__ out, int N) {
    int t = blockIdx.x * blockDim.x + threadIdx.x;
    int node = t >> 4, sub = t & 15;
    if (node >= N) return;

    uint2 pb = __ldg((const uint2*)(g_nh + (size_t)node * D) + sub);
    float2 b0 = __half22float2(*(const __half2*)&pb.x);
    float2 b1 = __half22float2(*(const __half2*)&pb.y);

    int base = g_off[node] + g_partoff[node >> 10];
    int cnt  = g_count[node];
    float bt = __ldg(beta);

    float ax = 0.f, ay = 0.f, az = 0.f, aw = 0.f, wsum = 0.f;
    for (int k = 0; k < cnt; k++) {
        int s = __ldg(&g_srcs[base + k]);
        uint2 pa = __ldg((const uint2*)(g_nh + (size_t)s * D) + sub);
        float2 a0 = __half22float2(*(const __half2*)&pa.x);
        float2 a1 = __half22float2(*(const __half2*)&pa.y);
        float p = a0.x * b0.x + a0.y * b0.y + a1.x * b1.x + a1.y * b1.y;
        #pragma unroll
        for (int o = 8; o; o >>= 1) p += __shfl_xor_sync(0xffffffffu, p, o);
        float w = __expf(bt * p);
        wsum += w;
        float wn = w * __ldg(&g_norm[s]);
        ax += wn * a0.x; ay += wn * a0.y; az += wn * a1.x; aw += wn * a1.y;
    }
    float inv = (cnt > 0) ? (1.0f / fmaxf(wsum, EPS)) : 0.0f;
    ((float4*)(out + (size_t)node * D))[sub] =
        make_float4(ax * inv, ay * inv, az * inv, aw * inv);
}

// ---------------------------------------------------------------------------
extern "C" void kernel_launch(void* const* d_in, const int* in_sizes, int n_in,
                              void* d_out, int out_size) {
    const float* feat = (const float*)d_in[0];
    const float* beta = (const float*)d_in[1];
    const int*   src  = (const int*)d_in[2];
    const int*   dst  = (const int*)d_in[3];
    float*       out  = (float*)d_out;

    int N = in_sizes[0] / D;
    int E = in_sizes[2];
    int nPart = (N + SCAN_BLK - 1) / SCAN_BLK;

    int node_threads = N * 16;
    k_norm<<<(node_threads + 255) / 256, 256>>>(feat, N);
    k_hist<<<(E + 255) / 256, 256>>>(dst, E);
    k_scan1<<<nPart, SCAN_BLK>>>(N);
    k_scan2<<<1, MAX_PART>>>(nPart);
    k_scatter<<<(E + 255) / 256, 256>>>(src, dst, E);
    k_agg<<<(node_threads + 255) / 256, 256>>>(beta, out, N);
}

// round 6
// speedup vs baseline: 1.5573x; 1.5573x over previous
#include <cuda_runtime.h>
#include <cuda_fp16.h>

#define D 64
#define MAXN 100000
#define MAXE 1200000
#define EPS 1e-12f

// Scratch (device globals — no allocation allowed in kernel_launch)
__device__ __half g_nh[(size_t)MAXN * D];  // normalized features, fp16, 12.8 MB
__device__ float  g_norm[MAXN];            // per-node L2 norm
__device__ float  g_psum[MAXN];            // per-dst softmax denominator

// ---------------------------------------------------------------------------
// K1: L2-normalize each node's row. 16 lanes per node, float4 per lane.
//     Stores nh fp16 + norm scalar (edge pass reconstructs feat = norm*nh),
//     zeroes psum.
// ---------------------------------------------------------------------------
__global__ void k_norm(const float* __restrict__ feat, int N) {
    int t = blockIdx.x * blockDim.x + threadIdx.x;
    int node = t >> 4, sub = t & 15;
    if (node >= N) return;
    float4 v = __ldg((const float4*)(feat + (size_t)node * D) + sub);
    float ss = v.x * v.x + v.y * v.y + v.z * v.z + v.w * v.w;
    #pragma unroll
    for (int o = 8; o; o >>= 1) ss += __shfl_xor_sync(0xffffffffu, ss, o);
    float nrm = fmaxf(sqrtf(ss), EPS);
    float inv = 1.0f / nrm;
    __half2 h0 = __floats2half2_rn(v.x * inv, v.y * inv);
    __half2 h1 = __floats2half2_rn(v.z * inv, v.w * inv);
    ((uint2*)(g_nh + (size_t)node * D))[sub] =
        make_uint2(*(const unsigned*)&h0, *(const unsigned*)&h1);
    if (sub == 0) { g_norm[node] = nrm; g_psum[node] = 0.0f; }
}

// ---------------------------------------------------------------------------
// K2 (fused edge pass): 8 lanes per edge, uint4 (16B = 8 fp16 dims) per lane.
//     - gather nh[src], nh[dst] (L2-resident, 128B/row)
//     - 3-level butterfly dot over the 8-lane group
//     - w = exp(beta*dot)  (softmax max-pass skipped: shift-invariant,
//       |beta*cos| <= |beta| so exp is safe)
//     - message from registers: feat[src] = norm[src]*nh[src] (no feat gather)
//     - two red.global.add.v4.f32 per lane into out[dst] (fire-and-forget)
//     - lane 0 of the group: red.global.add.f32 of w into psum[dst]
//     Softmax division hoisted to K3: out_i = (sum w*feat) / (sum w).
// ---------------------------------------------------------------------------
__global__ void k_edge(const int* __restrict__ src, const int* __restrict__ dst,
                       const float* __restrict__ beta,
                       float* __restrict__ out, int E) {
    int t = blockIdx.x * blockDim.x + threadIdx.x;
    int e = t >> 3;
    int sub = t & 7;
    if (e >= E) return;
    int s = __ldg(src + e), d = __ldg(dst + e);

    uint4 pa = __ldg((const uint4*)(g_nh + (size_t)s * D) + sub);
    uint4 pb = __ldg((const uint4*)(g_nh + (size_t)d * D) + sub);
    float2 a0 = __half22float2(*(const __half2*)&pa.x);
    float2 a1 = __half22float2(*(const __half2*)&pa.y);
    float2 a2 = __half22float2(*(const __half2*)&pa.z);
    float2 a3 = __half22float2(*(const __half2*)&pa.w);
    float2 b0 = __half22float2(*(const __half2*)&pb.x);
    float2 b1 = __half22float2(*(const __half2*)&pb.y);
    float2 b2 = __half22float2(*(const __half2*)&pb.z);
    float2 b3 = __half22float2(*(const __half2*)&pb.w);

    float p = a0.x * b0.x + a0.y * b0.y + a1.x * b1.x + a1.y * b1.y
            + a2.x * b2.x + a2.y * b2.y + a3.x * b3.x + a3.y * b3.y;
    #pragma unroll
    for (int o = 4; o; o >>= 1) p += __shfl_xor_sync(0xffffffffu, p, o);

    float w = __expf(__ldg(beta) * p);
    float wn = w * __ldg(&g_norm[s]);   // w * norm[src]: message scale

    float* addr = out + (size_t)d * D + sub * 8;
    asm volatile("red.global.add.v4.f32 [%0], {%1, %2, %3, %4};"
                 :: "l"(addr), "f"(a0.x * wn), "f"(a0.y * wn),
                    "f"(a1.x * wn), "f"(a1.y * wn) : "memory");
    asm volatile("red.global.add.v4.f32 [%0], {%1, %2, %3, %4};"
                 :: "l"(addr + 4), "f"(a2.x * wn), "f"(a2.y * wn),
                    "f"(a3.x * wn), "f"(a3.y * wn) : "memory");
    if (sub == 0) {
        asm volatile("red.global.add.f32 [%0], %1;"
                     :: "l"(&g_psum[d]), "f"(w) : "memory");
    }
}

// ---------------------------------------------------------------------------
// K3: per-node normalization: out[i] /= max(psum[i], EPS).
//     Isolated nodes: psum=0 and out row=0 -> stays 0 (matches reference).
// ---------------------------------------------------------------------------
__global__ void k_div(float* __restrict__ out, int N) {
    int t = blockIdx.x * blockDim.x + threadIdx.x;
    int node = t >> 4, sub = t & 15;
    if (node >= N) return;
    float inv = 1.0f / fmaxf(g_psum[node], EPS);
    float4* p = (float4*)(out + (size_t)node * D) + sub;
    float4 v = *p;
    v.x *= inv; v.y *= inv; v.z *= inv; v.w *= inv;
    *p = v;
}

// ---------------------------------------------------------------------------
extern "C" void kernel_launch(void* const* d_in, const int* in_sizes, int n_in,
                              void* d_out, int out_size) {
    const float* feat = (const float*)d_in[0];
    const float* beta = (const float*)d_in[1];
    const int*   src  = (const int*)d_in[2];
    const int*   dst  = (const int*)d_in[3];
    float*       out  = (float*)d_out;

    int N = in_sizes[0] / D;
    int E = in_sizes[2];

    // out accumulates via red.add, so it must start at zero.
    cudaMemsetAsync(out, 0, (size_t)out_size * sizeof(float));

    int node_threads = N * 16;
    k_norm<<<(node_threads + 255) / 256, 256>>>(feat, N);

    int edge_threads = E * 8;
    k_edge<<<(edge_threads + 255) / 256, 256>>>(src, dst, beta, out, E);

    k_div<<<(node_threads + 255) / 256, 256>>>(out, N);
}

// round 8
// speedup vs baseline: 1.7773x; 1.1413x over previous
#include <cuda_runtime.h>
#include <cuda_fp16.h>

#define D 64
#define MAXN 100000
#define MAXE 1200000
#define EPS 1e-12f

// Scratch (device globals — no allocation allowed in kernel_launch)
__device__ __half g_nh[(size_t)MAXN * D];  // normalized features, fp16, 12.8 MB
__device__ float  g_norm[MAXN];            // per-node L2 norm
__device__ float  g_psum[MAXN];            // per-dst softmax denominator

// 16-lane-group sum: 4-deep shfl.xor butterfly (redux.f32 is NOT in sm_103 ISA).
__device__ __forceinline__ float group16_sum(float p) {
    #pragma unroll
    for (int o = 8; o; o >>= 1) p += __shfl_xor_sync(0xffffffffu, p, o);
    return p;
}

// ---------------------------------------------------------------------------
// K1: L2-normalize each node's row. 16 lanes per node, float4 per lane.
//     Stores nh fp16 + norm scalar (edge pass reconstructs feat = norm*nh),
//     zeroes psum AND the node's out row (replaces the memset launch).
// ---------------------------------------------------------------------------
__global__ void k_norm(const float* __restrict__ feat, float* __restrict__ out, int N) {
    int t = blockIdx.x * blockDim.x + threadIdx.x;
    int node = t >> 4, sub = t & 15;
    if (node >= N) return;
    float4 v = __ldg((const float4*)(feat + (size_t)node * D) + sub);
    float ss = group16_sum(v.x * v.x + v.y * v.y + v.z * v.z + v.w * v.w);
    float nrm = fmaxf(sqrtf(ss), EPS);
    float inv = 1.0f / nrm;
    __half2 h0 = __floats2half2_rn(v.x * inv, v.y * inv);
    __half2 h1 = __floats2half2_rn(v.z * inv, v.w * inv);
    ((uint2*)(g_nh + (size_t)node * D))[sub] =
        make_uint2(*(const unsigned*)&h0, *(const unsigned*)&h1);
    ((float4*)(out + (size_t)node * D))[sub] = make_float4(0.f, 0.f, 0.f, 0.f);
    if (sub == 0) { g_norm[node] = nrm; g_psum[node] = 0.0f; }
}

// ---------------------------------------------------------------------------
// K2 (fused edge pass): 16 lanes per edge, uint2 (8B = 4 fp16 dims) per lane.
//     - gather nh[src], nh[dst] (L2-resident, 128B/row)
//     - 16-lane shfl dot; beta & norm[src] loads hoisted BEFORE the butterfly
//       so their latency overlaps the shfl chain
//     - w = exp(beta*dot)  (softmax max-pass skipped: shift-invariant,
//       |beta*cos| <= |beta| so exp is safe)
//     - message from registers: feat[src] = norm[src]*nh[src] (no feat gather)
//     - one red.global.add.v4.f32 per lane into out[dst] (fire-and-forget)
//     - lane 0: red.global.add.f32 of w into psum[dst]
//     Softmax division hoisted to K3: out_i = (sum w*feat) / (sum w).
// ---------------------------------------------------------------------------
__global__ void k_edge(const int* __restrict__ src, const int* __restrict__ dst,
                       const float* __restrict__ beta,
                       float* __restrict__ out, int E) {
    int t = blockIdx.x * blockDim.x + threadIdx.x;
    int e = t >> 4;
    int sub = t & 15;
    if (e >= E) return;
    int s = __ldg(src + e), d = __ldg(dst + e);

    uint2 pa = __ldg((const uint2*)(g_nh + (size_t)s * D) + sub);
    uint2 pb = __ldg((const uint2*)(g_nh + (size_t)d * D) + sub);
    float bt  = __ldg(beta);           // hoisted: overlap with shfl chain
    float nrm = __ldg(&g_norm[s]);     // hoisted: overlap with shfl chain

    float2 a0 = __half22float2(*(const __half2*)&pa.x);
    float2 a1 = __half22float2(*(const __half2*)&pa.y);
    float2 b0 = __half22float2(*(const __half2*)&pb.x);
    float2 b1 = __half22float2(*(const __half2*)&pb.y);
    float p = group16_sum(a0.x * b0.x + a0.y * b0.y + a1.x * b1.x + a1.y * b1.y);

    float w = __expf(bt * p);
    float wn = w * nrm;                // w * norm[src]: message scale

    float* addr = out + (size_t)d * D + sub * 4;
    asm volatile("red.global.add.v4.f32 [%0], {%1, %2, %3, %4};"
                 :: "l"(addr), "f"(a0.x * wn), "f"(a0.y * wn),
                    "f"(a1.x * wn), "f"(a1.y * wn)
                 : "memory");
    if (sub == 0) {
        asm volatile("red.global.add.f32 [%0], %1;"
                     :: "l"(&g_psum[d]), "f"(w) : "memory");
    }
}

// ---------------------------------------------------------------------------
// K3: per-node normalization: out[i] /= max(psum[i], EPS).
//     Isolated nodes: psum=0 and out row=0 -> stays 0 (matches reference).
// ---------------------------------------------------------------------------
__global__ void k_div(float* __restrict__ out, int N) {
    int t = blockIdx.x * blockDim.x + threadIdx.x;
    int node = t >> 4, sub = t & 15;
    if (node >= N) return;
    float inv = 1.0f / fmaxf(g_psum[node], EPS);
    float4* p = (float4*)(out + (size_t)node * D) + sub;
    float4 v = *p;
    v.x *= inv; v.y *= inv; v.z *= inv; v.w *= inv;
    *p = v;
}

// ---------------------------------------------------------------------------
extern "C" void kernel_launch(void* const* d_in, const int* in_sizes, int n_in,
                              void* d_out, int out_size) {
    const float* feat = (const float*)d_in[0];
    const float* beta = (const float*)d_in[1];
    const int*   src  = (const int*)d_in[2];
    const int*   dst  = (const int*)d_in[3];
    float*       out  = (float*)d_out;

    int N = in_sizes[0] / D;
    int E = in_sizes[2];

    int node_threads = N * 16;
    k_norm<<<(node_threads + 255) / 256, 256>>>(feat, out, N);

    int edge_threads = E * 16;
    k_edge<<<(edge_threads + 255) / 256, 256>>>(src, dst, beta, out, E);

    k_div<<<(node_threads + 255) / 256, 256>>>(out, N);
}

// round 9
// speedup vs baseline: 1.9868x; 1.1179x over previous
#include <cuda_runtime.h>
#include <cuda_fp16.h>

#define D 64
#define MAXN 100000
#define MAXE 1200000
#define EPS 1e-12f

// Scratch (device globals — no allocation allowed in kernel_launch)
__device__ __half g_nh[(size_t)MAXN * D];  // normalized features, fp16, 12.8 MB
__device__ float  g_norm[MAXN];            // per-node L2 norm
__device__ float  g_psum[MAXN];            // per-dst softmax denominator

__device__ __forceinline__ float group16_sum(float p) {
    #pragma unroll
    for (int o = 8; o; o >>= 1) p += __shfl_xor_sync(0xffffffffu, p, o);
    return p;
}

// ---------------------------------------------------------------------------
// K1: L2-normalize each node's row. 16 lanes per node, float4 per lane.
//     Stores nh fp16 + norm scalar (edge pass reconstructs feat = norm*nh),
//     zeroes psum. (out zeroed by the async memset — measured faster than
//     folding the zeroing in here.)
// ---------------------------------------------------------------------------
__global__ void k_norm(const float* __restrict__ feat, int N) {
    int t = blockIdx.x * blockDim.x + threadIdx.x;
    int node = t >> 4, sub = t & 15;
    if (node >= N) return;
    float4 v = __ldg((const float4*)(feat + (size_t)node * D) + sub);
    float ss = group16_sum(v.x * v.x + v.y * v.y + v.z * v.z + v.w * v.w);
    float nrm = fmaxf(sqrtf(ss), EPS);
    float inv = 1.0f / nrm;
    __half2 h0 = __floats2half2_rn(v.x * inv, v.y * inv);
    __half2 h1 = __floats2half2_rn(v.z * inv, v.w * inv);
    ((uint2*)(g_nh + (size_t)node * D))[sub] =
        make_uint2(*(const unsigned*)&h0, *(const unsigned*)&h1);
    if (sub == 0) { g_norm[node] = nrm; g_psum[node] = 0.0f; }
}

// ---------------------------------------------------------------------------
// K2 (fused edge pass, ILP=2): 16 lanes per edge-pair; each thread owns
//     edge e and edge e+half — two INDEPENDENT dependency chains that the
//     scheduler interleaves, doubling per-thread MLP (the kernel is
//     latency-exposed above its ~57us LTS byte floor, not byte-bound).
//     Per edge:
//     - gather nh[src], nh[dst] fp16 (L2-resident)
//     - 16-lane shfl dot; w = exp(beta*dot)  (max-pass skipped: shift-
//       invariant softmax, |beta*cos| <= |beta| so exp is safe)
//     - message from registers: feat[src] = norm[src]*nh[src]
//     - red.global.add.v4.f32 into out[dst]; lane0 red of w into psum[dst]
//     Softmax division hoisted to K3: out_i = (sum w*feat) / (sum w).
// ---------------------------------------------------------------------------
__global__ void k_edge(const int* __restrict__ src, const int* __restrict__ dst,
                       const float* __restrict__ beta,
                       float* __restrict__ out, int E, int half) {
    int t = blockIdx.x * blockDim.x + threadIdx.x;
    int e1 = t >> 4;
    int sub = t & 15;
    if (e1 >= half) return;
    int e2 = e1 + half;
    bool has2 = (e2 < E);

    // --- front-batch all loads (both edges) for maximum MLP ---
    int s1 = __ldg(src + e1), d1 = __ldg(dst + e1);
    int s2 = has2 ? __ldg(src + e2) : s1;
    int d2 = has2 ? __ldg(dst + e2) : d1;

    uint2 pa1 = __ldg((const uint2*)(g_nh + (size_t)s1 * D) + sub);
    uint2 pb1 = __ldg((const uint2*)(g_nh + (size_t)d1 * D) + sub);
    uint2 pa2 = __ldg((const uint2*)(g_nh + (size_t)s2 * D) + sub);
    uint2 pb2 = __ldg((const uint2*)(g_nh + (size_t)d2 * D) + sub);
    float n1 = __ldg(&g_norm[s1]);
    float n2 = __ldg(&g_norm[s2]);
    float bt = __ldg(beta);

    float2 a10 = __half22float2(*(const __half2*)&pa1.x);
    float2 a11 = __half22float2(*(const __half2*)&pa1.y);
    float2 b10 = __half22float2(*(const __half2*)&pb1.x);
    float2 b11 = __half22float2(*(const __half2*)&pb1.y);
    float2 a20 = __half22float2(*(const __half2*)&pa2.x);
    float2 a21 = __half22float2(*(const __half2*)&pa2.y);
    float2 b20 = __half22float2(*(const __half2*)&pb2.x);
    float2 b21 = __half22float2(*(const __half2*)&pb2.y);

    // two independent shfl chains — interleaved by the scheduler
    float p1 = a10.x * b10.x + a10.y * b10.y + a11.x * b11.x + a11.y * b11.y;
    float p2 = a20.x * b20.x + a20.y * b20.y + a21.x * b21.x + a21.y * b21.y;
    #pragma unroll
    for (int o = 8; o; o >>= 1) {
        p1 += __shfl_xor_sync(0xffffffffu, p1, o);
        p2 += __shfl_xor_sync(0xffffffffu, p2, o);
    }

    float w1 = __expf(bt * p1);
    float w2 = __expf(bt * p2);
    float wn1 = w1 * n1;
    float wn2 = w2 * n2;

    float* adr1 = out + (size_t)d1 * D + sub * 4;
    asm volatile("red.global.add.v4.f32 [%0], {%1, %2, %3, %4};"
                 :: "l"(adr1), "f"(a10.x * wn1), "f"(a10.y * wn1),
                    "f"(a11.x * wn1), "f"(a11.y * wn1) : "memory");
    if (has2) {
        float* adr2 = out + (size_t)d2 * D + sub * 4;
        asm volatile("red.global.add.v4.f32 [%0], {%1, %2, %3, %4};"
                     :: "l"(adr2), "f"(a20.x * wn2), "f"(a20.y * wn2),
                        "f"(a21.x * wn2), "f"(a21.y * wn2) : "memory");
    }
    if (sub == 0) {
        asm volatile("red.global.add.f32 [%0], %1;"
                     :: "l"(&g_psum[d1]), "f"(w1) : "memory");
        if (has2)
            asm volatile("red.global.add.f32 [%0], %1;"
                         :: "l"(&g_psum[d2]), "f"(w2) : "memory");
    }
}

// ---------------------------------------------------------------------------
// K3: per-node normalization: out[i] /= max(psum[i], EPS).
//     Isolated nodes: psum=0 and out row=0 -> stays 0 (matches reference).
// ---------------------------------------------------------------------------
__global__ void k_div(float* __restrict__ out, int N) {
    int t = blockIdx.x * blockDim.x + threadIdx.x;
    int node = t >> 4, sub = t & 15;
    if (node >= N) return;
    float inv = 1.0f / fmaxf(g_psum[node], EPS);
    float4* p = (float4*)(out + (size_t)node * D) + sub;
    float4 v = *p;
    v.x *= inv; v.y *= inv; v.z *= inv; v.w *= inv;
    *p = v;
}

// ---------------------------------------------------------------------------
extern "C" void kernel_launch(void* const* d_in, const int* in_sizes, int n_in,
                              void* d_out, int out_size) {
    const float* feat = (const float*)d_in[0];
    const float* beta = (const float*)d_in[1];
    const int*   src  = (const int*)d_in[2];
    const int*   dst  = (const int*)d_in[3];
    float*       out  = (float*)d_out;

    int N = in_sizes[0] / D;
    int E = in_sizes[2];
    int half = (E + 1) / 2;

    // out accumulates via red.add, so it must start at zero.
    cudaMemsetAsync(out, 0, (size_t)out_size * sizeof(float));

    int node_threads = N * 16;
    k_norm<<<(node_threads + 255) / 256, 256>>>(feat, N);

    int edge_threads = half * 16;
    k_edge<<<(edge_threads + 255) / 256, 256>>>(src, dst, beta, out, E, half);

    k_div<<<(node_threads + 255) / 256, 256>>>(out, N);
}